// round 13
// baseline (speedup 1.0000x reference)
#include <cuda_runtime.h>
#include <cuda_bf16.h>

#define HH 256
#define WW 256
#define NMASK 64
#define CDIM 81
#define BQ 200
#define HW (HH*WW)
#define NBX 2            // w-tiles per row (256/128)
#define NBY 32           // h-tiles (256/8)
#define NBLK (NBX*NBY*NMASK)   // 4096 pair blocks

// All communication via plain stores into per-block slots -> no init pass,
// no atomics, no cross-replay state (every word rewritten each replay).
__device__ float  g_pairsum[NBLK];
__device__ float  g_paircnt[NBLK];
__device__ float  g_rowpmax[NMASK * HH * NBX];   // [n][h][bx]
__device__ int    g_rowpbox[NMASK * HH * NBX];
__device__ float  g_colpmax[NMASK * NBY * WW];   // [n][by][w]
__device__ int    g_colpbox[NMASK * NBY * WW];
__device__ float  g_cepart[25 * 2];              // per-CE-block (wnll, wsum)
__device__ double g_projpart[NMASK];             // per-n lx+ly
__device__ double g_pp2[NMASK * 2];              // per-n (pair sum, cnt)

// Fast softplus: 2 MUFU + few FMA. Abs err ~1e-7, fine vs 1e-3 tolerance.
__device__ __forceinline__ float softplusf(float z) {
    return fmaxf(z, 0.f) + __logf(1.f + __expf(-fabsf(z)));
}

// ---------------------------------------------------------------------------
// Cross-entropy: warp per row, coalesced lane-strided class loads.
// 25 blocks x 8 warps = 200 rows. Block partial -> plain store.
__global__ void ce_kernel(const float* __restrict__ logits,
                          const int* __restrict__ cls,
                          const float* __restrict__ ew) {
    const int wid = threadIdx.x >> 5, lane = threadIdx.x & 31;
    const int row = blockIdx.x * 8 + wid;
    const float* p = logits + row * CDIM;

    float v0 = p[lane];
    float v1 = p[lane + 32];
    float v2 = (lane < CDIM - 64) ? p[lane + 64] : -1e30f;
    float mx = fmaxf(v0, fmaxf(v1, v2));
    #pragma unroll
    for (int o = 16; o > 0; o >>= 1)
        mx = fmaxf(mx, __shfl_xor_sync(0xffffffff, mx, o));
    float se = __expf(v0 - mx) + __expf(v1 - mx) +
               ((lane < CDIM - 64) ? __expf(v2 - mx) : 0.f);
    #pragma unroll
    for (int o = 16; o > 0; o >>= 1)
        se += __shfl_xor_sync(0xffffffff, se, o);

    int t = cls[row];
    float w = ew[t];
    float wn = -w * (p[t] - mx - __logf(se));

    __shared__ float s1[8], s2[8];
    if (lane == 0) { s1[wid] = wn; s2[wid] = w; }
    __syncthreads();
    if (threadIdx.x == 0) {
        float a = 0.f, b = 0.f;
        #pragma unroll
        for (int i = 0; i < 8; i++) { a += s1[i]; b += s2[i]; }
        g_cepart[blockIdx.x * 2 + 0] = a;
        g_cepart[blockIdx.x * 2 + 1] = b;
    }
}

// ---------------------------------------------------------------------------
// Fused pairwise + projection-max pass. Tile: 128 wide x 8 high per block
// (256 threads, 4 px/thread, 128-bit loads). sims float4s are converted to
// threshold bits immediately after load. Inner loop is a bit-walk over
// surviving (box & thresh & in-bounds) pairs. All outputs = plain stores.
__global__ __launch_bounds__(256, 6)
void pair_kernel(const float* __restrict__ src,
                 const float* __restrict__ sims,
                 const int* __restrict__ box) {
    const int n = blockIdx.z;
    const int by = blockIdx.y;
    const int bx = blockIdx.x;
    const int h0 = by * 8;
    const int w0 = bx * 128;
    const int tx = threadIdx.x;       // 0..31
    const int ty = threadIdx.y;       // 0..7
    const int tid = ty * 32 + tx;

    __shared__ float sxf[12 * 132];   // src values, 2-px halo (flat)
    __shared__ float sspf[12 * 132];  // softplus(src)
    __shared__ int   sb[8][128];      // box tile
    __shared__ int   nboff[8];        // neighbor offsets in flat tile

    const int h = h0 + ty;
    const int wbase = w0 + tx * 4;

    if (tid < 8) {
        const int di[8] = {-2, -2, -2, 0, 0, 2, 2, 2};
        const int dj[8] = {-2, 0, 2, -2, 2, -2, 0, 2};
        nboff[tid] = di[tid] * 132 + dj[tid];
    }

    // Front-batched wide loads, converted to bits as they land.
    const float* simp = sims + (size_t)n * 8 * HW + h * WW + wbase;
    unsigned m = 0;
    #pragma unroll
    for (int p = 0; p < 8; p++) {
        float4 v = __ldcs((const float4*)(simp + (size_t)p * HW));
        m |= (v.x >= 0.3f ? 1u : 0u) << (0 * 8 + p);
        m |= (v.y >= 0.3f ? 1u : 0u) << (1 * 8 + p);
        m |= (v.z >= 0.3f ? 1u : 0u) << (2 * 8 + p);
        m |= (v.w >= 0.3f ? 1u : 0u) << (3 * 8 + p);
    }
    int4 b4 = __ldcs((const int4*)(box + (size_t)n * HW + h * WW + wbase));

    // Fill shared src tile (+ halo) and softplus.
    const float* srcn = src + (size_t)n * HW;
    for (int idx = tid; idx < 12 * 132; idx += 256) {
        int r = idx / 132, c = idx - r * 132;
        int gh = h0 - 2 + r, gw = w0 - 2 + c;
        float x = 0.f;
        if ((unsigned)gh < HH && (unsigned)gw < WW) x = srcn[gh * WW + gw];
        sxf[idx] = x;
        sspf[idx] = softplusf(x);
    }
    sb[ty][tx * 4 + 0] = b4.x;
    sb[ty][tx * 4 + 1] = b4.y;
    sb[ty][tx * 4 + 2] = b4.z;
    sb[ty][tx * 4 + 3] = b4.w;

    // Box gate and tgt count (counted BEFORE OOB masking — reference counts
    // tgt over all taps including zero-padded ones).
    unsigned bm = (b4.x ? 0x000000FFu : 0u) | (b4.y ? 0x0000FF00u : 0u) |
                  (b4.z ? 0x00FF0000u : 0u) | (b4.w ? 0xFF000000u : 0u);
    m &= bm;
    float cnt = (float)__popc(m);
    int rbox = (b4.x | b4.y | b4.z | b4.w);

    // OOB allow-mask: only border threads lose bits.
    {
        unsigned rowbad = (h < 2 ? 0x07u : 0u) | (h > 253 ? 0xE0u : 0u);
        unsigned am = 0;
        #pragma unroll
        for (int i = 0; i < 4; i++) {
            int w = wbase + i;
            unsigned bad = rowbad | (w < 2 ? 0x29u : 0u) | (w > 253 ? 0x94u : 0u);
            am |= (0xFFu & ~bad) << (8 * i);
        }
        m &= am;
    }
    __syncthreads();

    // Bit-walk over surviving pairs.
    const int cbase = (ty + 2) * 132 + tx * 4 + 2;
    float sum = 0.f;
    float rmax = -1e30f;
    #pragma unroll
    for (int i = 0; i < 4; i++) rmax = fmaxf(rmax, sxf[cbase + i]);

    while (m) {
        int b = __ffs(m) - 1;
        m &= m - 1;
        int i = b >> 3, p = b & 7;
        int ci = cbase + i;
        int off = nboff[p];
        float xc = sxf[ci];
        float spc = sspf[ci];
        float xn = sxf[ci + off];
        float spn = sspf[ci + off];
        float z = xc + xn;
        sum += spc + spn - (fmaxf(z, 0.f) + __logf(1.f + __expf(-fabsf(z))));
    }

    // Per-row (warp) reduce: pairwise sums + row max/box -> plain stores.
    #pragma unroll
    for (int o = 16; o > 0; o >>= 1) {
        sum += __shfl_down_sync(0xffffffff, sum, o);
        cnt += __shfl_down_sync(0xffffffff, cnt, o);
        rmax = fmaxf(rmax, __shfl_xor_sync(0xffffffff, rmax, o));
        rbox |= __shfl_xor_sync(0xffffffff, rbox, o);
    }
    if (tx == 0) {
        g_rowpmax[(n * HH + h) * NBX + bx] = rmax;
        g_rowpbox[(n * HH + h) * NBX + bx] = rbox;
    }

    // Column partials from the shared tile (threads 0..127, one column each).
    if (tid < 128) {
        const int c = tid;
        float mx = -1e30f; int ob = 0;
        #pragma unroll
        for (int r = 0; r < 8; r++) {
            mx = fmaxf(mx, sxf[(r + 2) * 132 + c + 2]);
            ob |= sb[r][c];
        }
        g_colpmax[(n * NBY + by) * WW + w0 + c] = mx;
        g_colpbox[(n * NBY + by) * WW + w0 + c] = ob;
    }

    // Block pairwise partial -> plain store.
    __shared__ float rs[8], rc[8];
    if (tx == 0) { rs[ty] = sum; rc[ty] = cnt; }
    __syncthreads();
    if (tid == 0) {
        float S = 0.f, C = 0.f;
        #pragma unroll
        for (int i2 = 0; i2 < 8; i2++) { S += rs[i2]; C += rc[i2]; }
        int blin = bx + NBX * (by + NBY * n);
        g_pairsum[blin] = S;
        g_paircnt[blin] = C;
    }
}

// ---------------------------------------------------------------------------
// Projection finish (64 blocks, one per n): dice term for n + reduce this n's
// slice of pair partials. Plain stores.
__global__ void projfinish_kernel() {
    const int n = blockIdx.x;
    const int t = threadIdx.x;   // 0..255

    // Row side: combine NBX partials.
    float mr = fmaxf(g_rowpmax[(n * HH + t) * NBX + 0],
                     g_rowpmax[(n * HH + t) * NBX + 1]);
    int rb = g_rowpbox[(n * HH + t) * NBX + 0] | g_rowpbox[(n * HH + t) * NBX + 1];
    float ix = 1.f / (1.f + __expf(-mr));
    float txv = (float)(rb ? 1 : 0);
    float a0 = ix * txv, a1 = ix * ix, a2 = txv * txv;

    // Col side: combine NBY partials (coalesced across t).
    float mc = -1e30f; int cb = 0;
    #pragma unroll 4
    for (int by = 0; by < NBY; by++) {
        mc = fmaxf(mc, g_colpmax[(n * NBY + by) * WW + t]);
        cb |= g_colpbox[(n * NBY + by) * WW + t];
    }
    float iy = 1.f / (1.f + __expf(-mc));
    float tyv = (float)(cb ? 1 : 0);
    float b0 = iy * tyv, b1 = iy * iy, b2 = tyv * tyv;

    // Pair-partial slice (64 entries for this n).
    float ps = 0.f, pc = 0.f;
    if (t < 64) { ps = g_pairsum[n * 64 + t]; pc = g_paircnt[n * 64 + t]; }

    #pragma unroll
    for (int o = 16; o > 0; o >>= 1) {
        a0 += __shfl_down_sync(0xffffffff, a0, o);
        a1 += __shfl_down_sync(0xffffffff, a1, o);
        a2 += __shfl_down_sync(0xffffffff, a2, o);
        b0 += __shfl_down_sync(0xffffffff, b0, o);
        b1 += __shfl_down_sync(0xffffffff, b1, o);
        b2 += __shfl_down_sync(0xffffffff, b2, o);
        ps += __shfl_down_sync(0xffffffff, ps, o);
        pc += __shfl_down_sync(0xffffffff, pc, o);
    }
    __shared__ float r[8][8];
    int wid = t >> 5, lane = t & 31;
    if (lane == 0) {
        r[0][wid] = a0; r[1][wid] = a1; r[2][wid] = a2;
        r[3][wid] = b0; r[4][wid] = b1; r[5][wid] = b2;
        r[6][wid] = ps; r[7][wid] = pc;
    }
    __syncthreads();
    if (t == 0) {
        float s[8] = {0, 0, 0, 0, 0, 0, 0, 0};
        #pragma unroll
        for (int i = 0; i < 8; i++)
            #pragma unroll
            for (int k = 0; k < 8; k++) s[k] += r[k][i];
        double lx = 1.0 - 2.0 * (double)s[0] / ((double)s[1] + (double)s[2] + 1e-3);
        double ly = 1.0 - 2.0 * (double)s[3] / ((double)s[4] + (double)s[5] + 1e-3);
        g_projpart[n] = lx + ly;
        g_pp2[n * 2 + 0] = (double)s[6];
        g_pp2[n * 2 + 1] = (double)s[7];
    }
}

// ---------------------------------------------------------------------------
// Final: one block combines 64 proj + 64x2 pair + 25x2 ce partials.
__global__ void final_kernel(const int* __restrict__ num_masks_p,
                             float* __restrict__ out) {
    const int t = threadIdx.x;   // 0..63
    double pj = (t < NMASK) ? g_projpart[t] : 0.0;
    double ps = (t < NMASK) ? g_pp2[t * 2 + 0] : 0.0;
    double pc = (t < NMASK) ? g_pp2[t * 2 + 1] : 0.0;
    float cn = (t < 25) ? g_cepart[t * 2 + 0] : 0.f;
    float cw = (t < 25) ? g_cepart[t * 2 + 1] : 0.f;

    __shared__ double sh[3][64];
    __shared__ float shc[2][64];
    sh[0][t] = pj; sh[1][t] = ps; sh[2][t] = pc;
    shc[0][t] = cn; shc[1][t] = cw;
    __syncthreads();
    for (int o = 32; o > 0; o >>= 1) {
        if (t < o) {
            sh[0][t] += sh[0][t + o];
            sh[1][t] += sh[1][t + o];
            sh[2][t] += sh[2][t + o];
            shc[0][t] += shc[0][t + o];
            shc[1][t] += shc[1][t + o];
        }
        __syncthreads();
    }
    if (t == 0) {
        int v = num_masks_p[0];
        if (v <= 0 || v > 1000000) {
            float f = __int_as_float(v);
            v = (int)f;
        }
        double nm = (double)max(v, 1);
        double ce = (double)shc[0][0] / (double)shc[1][0];
        double pair = sh[1][0] / fmax(sh[2][0], 1.0) / nm;
        double proj = sh[0][0] / nm;
        out[0] = (float)(ce + pair + proj);
    }
}

// ---------------------------------------------------------------------------
extern "C" void kernel_launch(void* const* d_in, const int* in_sizes, int n_in,
                              void* d_out, int out_size) {
    const float* pred_logits = (const float*)d_in[0];   // (2,100,81)
    const float* src_masks   = (const float*)d_in[1];   // (64,256,256)
    const float* empty_w     = (const float*)d_in[2];   // (81,)
    const float* sims        = (const float*)d_in[3];   // (64,8,256,256)
    const int*   tgt_cls     = (const int*)d_in[4];     // (2,100)
    const int*   box         = (const int*)d_in[5];     // (64,256,256)
    const int*   num_masks   = (const int*)d_in[6];     // scalar
    float* out = (float*)d_out;

    ce_kernel<<<25, 256>>>(pred_logits, tgt_cls, empty_w);
    pair_kernel<<<dim3(NBX, NBY, NMASK), dim3(32, 8)>>>(src_masks, sims, box);
    projfinish_kernel<<<NMASK, 256>>>();
    final_kernel<<<1, 64>>>(num_masks, out);
}

// round 14
// speedup vs baseline: 1.3832x; 1.3832x over previous
#include <cuda_runtime.h>
#include <cuda_bf16.h>

#define HH 256
#define WW 256
#define NMASK 64
#define CDIM 81
#define BQ 200
#define HW (HH*WW)

// Accumulators (device globals; no mallocs allowed).
__device__ double g_acc[5];  // 0: ce wnll, 1: ce wsum, 2: pair sum, 3: tgt cnt, 4: proj sum
__device__ unsigned g_rowmax[NMASK * HH];
__device__ unsigned g_colmax[NMASK * WW];
__device__ int g_rowbox[NMASK * HH];
__device__ int g_colbox[NMASK * WW];
__device__ int g_done;

__device__ __forceinline__ unsigned fenc(float f) {
    unsigned u = __float_as_uint(f);
    return (u & 0x80000000u) ? ~u : (u | 0x80000000u);
}
__device__ __forceinline__ float fdec(unsigned u) {
    return (u & 0x80000000u) ? __uint_as_float(u & 0x7fffffffu) : __uint_as_float(~u);
}
// Fast softplus: 2 MUFU + few FMA. Abs err ~1e-7, fine vs 1e-3 tolerance.
__device__ __forceinline__ float softplusf(float z) {
    return fmaxf(z, 0.f) + __logf(1.f + __expf(-fabsf(z)));
}

// ---------------------------------------------------------------------------
// Fused init + cross-entropy. Grid 65 x 256:
//   blocks 0..63  : zero the row/col max/box arrays (16384 words each)
//   block  64     : CE, warp-per-row coalesced (8 warps x 25 rows)
__global__ void setup_kernel(const float* __restrict__ logits,
                             const int* __restrict__ cls,
                             const float* __restrict__ ew) {
    if (blockIdx.x < 64) {
        int i = blockIdx.x * 256 + threadIdx.x;   // covers 16384 = NMASK*HH exactly
        g_rowmax[i] = 0u; g_rowbox[i] = 0;
        g_colmax[i] = 0u; g_colbox[i] = 0;
        if (blockIdx.x == 0 && threadIdx.x == 0) {
            g_acc[2] = 0.0; g_acc[3] = 0.0; g_acc[4] = 0.0; g_done = 0;
        }
        return;
    }

    // CE block: warp w handles rows w, w+8, ..., w+192.
    const int wid = threadIdx.x >> 5, lane = threadIdx.x & 31;
    float wn = 0.f, wv = 0.f;
    for (int r = 0; r < 25; r++) {
        const int row = wid + r * 8;   // < 200
        const float* p = logits + row * CDIM;
        float v0 = p[lane];
        float v1 = p[lane + 32];
        float v2 = (lane < CDIM - 64) ? p[lane + 64] : -1e30f;
        float mx = fmaxf(v0, fmaxf(v1, v2));
        #pragma unroll
        for (int o = 16; o > 0; o >>= 1)
            mx = fmaxf(mx, __shfl_xor_sync(0xffffffff, mx, o));
        float se = __expf(v0 - mx) + __expf(v1 - mx) +
                   ((lane < CDIM - 64) ? __expf(v2 - mx) : 0.f);
        #pragma unroll
        for (int o = 16; o > 0; o >>= 1)
            se += __shfl_xor_sync(0xffffffff, se, o);
        if (lane == 0) {
            int t = cls[row];
            float w = ew[t];
            wn += -w * (p[t] - mx - __logf(se));
            wv += w;
        }
    }
    __shared__ float s1[8], s2[8];
    if (lane == 0) { s1[wid] = wn; s2[wid] = wv; }
    __syncthreads();
    if (threadIdx.x == 0) {
        float a = 0.f, b = 0.f;
        #pragma unroll
        for (int i = 0; i < 8; i++) { a += s1[i]; b += s2[i]; }
        g_acc[0] = (double)a;
        g_acc[1] = (double)b;
    }
}

// ---------------------------------------------------------------------------
// Fused pairwise + projection-max pass. Tile: 128 wide x 8 high per block
// (256 threads, 4 px/thread, 128-bit loads). sims float4s are converted to
// threshold bits IMMEDIATELY after load (kills 32 regs of live payload ->
// higher occupancy). Inner loop is a bit-walk over surviving (box & thresh)
// pairs only. sim = sp(xc)+sp(xn)-sp(xc+xn); OOB neighbors contribute 0.
__global__ __launch_bounds__(256, 6)
void pair_kernel(const float* __restrict__ src,
                 const float* __restrict__ sims,
                 const int* __restrict__ box) {
    const int n = blockIdx.z;
    const int h0 = blockIdx.y * 8;
    const int w0 = blockIdx.x * 128;
    const int tx = threadIdx.x;       // 0..31
    const int ty = threadIdx.y;       // 0..7
    const int tid = ty * 32 + tx;

    __shared__ float sxf[12 * 132];   // src values, 2-px halo (flat)
    __shared__ float sspf[12 * 132];  // softplus(src)
    __shared__ int   sb[8][128];      // box tile
    __shared__ int   nboff[8];        // neighbor offsets in flat tile

    const int h = h0 + ty;
    const int wbase = w0 + tx * 4;

    if (tid < 8) {
        const int di[8] = {-2, -2, -2, 0, 0, 2, 2, 2};
        const int dj[8] = {-2, 0, 2, -2, 2, -2, 0, 2};
        nboff[tid] = di[tid] * 132 + dj[tid];
    }

    // Front-batched wide loads, converted to bits as they land.
    const float* simp = sims + (size_t)n * 8 * HW + h * WW + wbase;
    unsigned m = 0;
    #pragma unroll
    for (int p = 0; p < 8; p++) {
        float4 v = __ldcs((const float4*)(simp + (size_t)p * HW));
        m |= (v.x >= 0.3f ? 1u : 0u) << (0 * 8 + p);
        m |= (v.y >= 0.3f ? 1u : 0u) << (1 * 8 + p);
        m |= (v.z >= 0.3f ? 1u : 0u) << (2 * 8 + p);
        m |= (v.w >= 0.3f ? 1u : 0u) << (3 * 8 + p);
    }
    int4 b4 = __ldcs((const int4*)(box + (size_t)n * HW + h * WW + wbase));

    // Fill shared src tile (+ halo) and softplus.
    const float* srcn = src + (size_t)n * HW;
    for (int idx = tid; idx < 12 * 132; idx += 256) {
        int r = idx / 132, c = idx - r * 132;
        int gh = h0 - 2 + r, gw = w0 - 2 + c;
        float x = 0.f;
        if ((unsigned)gh < HH && (unsigned)gw < WW) x = srcn[gh * WW + gw];
        sxf[idx] = x;
        sspf[idx] = softplusf(x);
    }
    sb[ty][tx * 4 + 0] = b4.x;
    sb[ty][tx * 4 + 1] = b4.y;
    sb[ty][tx * 4 + 2] = b4.z;
    sb[ty][tx * 4 + 3] = b4.w;

    // Box gate (whole bytes) and tgt count (before OOB masking — reference
    // counts tgt over all taps including zero-padded ones).
    unsigned bm = (b4.x ? 0x000000FFu : 0u) | (b4.y ? 0x0000FF00u : 0u) |
                  (b4.z ? 0x00FF0000u : 0u) | (b4.w ? 0xFF000000u : 0u);
    m &= bm;
    float cnt = (float)__popc(m);
    int rbox = (b4.x | b4.y | b4.z | b4.w);

    // OOB allow-mask: only border threads lose bits.
    // bit p: di[p]=-2 for p<3 (+row<2 bad), di[p]=+2 for p>4; dj=-2 for p in
    // {0,3,5} (0x29), dj=+2 for p in {2,4,7} (0x94).
    {
        unsigned rowbad = (h < 2 ? 0x07u : 0u) | (h > 253 ? 0xE0u : 0u);
        unsigned am = 0;
        #pragma unroll
        for (int i = 0; i < 4; i++) {
            int w = wbase + i;
            unsigned bad = rowbad | (w < 2 ? 0x29u : 0u) | (w > 253 ? 0x94u : 0u);
            am |= (0xFFu & ~bad) << (8 * i);
        }
        m &= am;
    }
    __syncthreads();

    // Bit-walk over surviving pairs.
    const int cbase = (ty + 2) * 132 + tx * 4 + 2;
    float sum = 0.f;
    float rmax = -1e30f;
    #pragma unroll
    for (int i = 0; i < 4; i++) rmax = fmaxf(rmax, sxf[cbase + i]);

    while (m) {
        int b = __ffs(m) - 1;
        m &= m - 1;
        int i = b >> 3, p = b & 7;
        int ci = cbase + i;
        int off = nboff[p];
        float xc = sxf[ci];
        float spc = sspf[ci];
        float xn = sxf[ci + off];
        float spn = sspf[ci + off];
        float z = xc + xn;
        sum += spc + spn - (fmaxf(z, 0.f) + __logf(1.f + __expf(-fabsf(z))));
    }

    // Per-row (warp) reduce: pairwise sums + row max/box.
    #pragma unroll
    for (int o = 16; o > 0; o >>= 1) {
        sum += __shfl_down_sync(0xffffffff, sum, o);
        cnt += __shfl_down_sync(0xffffffff, cnt, o);
        rmax = fmaxf(rmax, __shfl_xor_sync(0xffffffff, rmax, o));
        rbox |= __shfl_xor_sync(0xffffffff, rbox, o);
    }
    if (tx == 0) {
        atomicMax(&g_rowmax[n * HH + h], fenc(rmax));
        if (rbox) g_rowbox[n * HH + h] = 1;   // idempotent store
    }

    // Column partials from the shared tile (threads 0..127, one column each).
    if (tid < 128) {
        const int c = tid;
        float mx = -1e30f; int ob = 0;
        #pragma unroll
        for (int r = 0; r < 8; r++) {
            mx = fmaxf(mx, sxf[(r + 2) * 132 + c + 2]);
            ob |= sb[r][c];
        }
        atomicMax(&g_colmax[n * WW + w0 + c], fenc(mx));
        if (ob) g_colbox[n * WW + w0 + c] = 1;
    }

    // Block reduce pairwise sums -> one double atomic each.
    __shared__ float rs[8], rc[8];
    if (tx == 0) { rs[ty] = sum; rc[ty] = cnt; }
    __syncthreads();
    if (tid == 0) {
        float S = 0.f, C = 0.f;
        #pragma unroll
        for (int i2 = 0; i2 < 8; i2++) { S += rs[i2]; C += rc[i2]; }
        atomicAdd(&g_acc[2], (double)S);
        atomicAdd(&g_acc[3], (double)C);
    }
}

// ---------------------------------------------------------------------------
// Projection finish (64 blocks, one per n) with fused final: the LAST block
// to complete computes the output scalar — no separate serial kernel.
__global__ void projfinish_kernel(const int* __restrict__ num_masks_p,
                                  float* __restrict__ out) {
    const int n = blockIdx.x;
    const int t = threadIdx.x;   // 0..255

    float mr = fdec(g_rowmax[n * HH + t]);
    float ix = 1.f / (1.f + __expf(-mr));
    float txv = (float)g_rowbox[n * HH + t];
    float a0 = ix * txv, a1 = ix * ix, a2 = txv * txv;

    float mc = fdec(g_colmax[n * WW + t]);
    float iy = 1.f / (1.f + __expf(-mc));
    float tyv = (float)g_colbox[n * WW + t];
    float b0 = iy * tyv, b1 = iy * iy, b2 = tyv * tyv;

    #pragma unroll
    for (int o = 16; o > 0; o >>= 1) {
        a0 += __shfl_down_sync(0xffffffff, a0, o);
        a1 += __shfl_down_sync(0xffffffff, a1, o);
        a2 += __shfl_down_sync(0xffffffff, a2, o);
        b0 += __shfl_down_sync(0xffffffff, b0, o);
        b1 += __shfl_down_sync(0xffffffff, b1, o);
        b2 += __shfl_down_sync(0xffffffff, b2, o);
    }
    __shared__ float r[6][8];
    int wid = t >> 5, lane = t & 31;
    if (lane == 0) {
        r[0][wid] = a0; r[1][wid] = a1; r[2][wid] = a2;
        r[3][wid] = b0; r[4][wid] = b1; r[5][wid] = b2;
    }
    __syncthreads();
    if (t == 0) {
        float s[6] = {0, 0, 0, 0, 0, 0};
        #pragma unroll
        for (int i = 0; i < 8; i++)
            #pragma unroll
            for (int k = 0; k < 6; k++) s[k] += r[k][i];
        double lx = 1.0 - 2.0 * (double)s[0] / ((double)s[1] + (double)s[2] + 1e-3);
        double ly = 1.0 - 2.0 * (double)s[3] / ((double)s[4] + (double)s[5] + 1e-3);
        atomicAdd(&g_acc[4], lx + ly);
        __threadfence();
        int prev = atomicAdd(&g_done, 1);
        if (prev == NMASK - 1) {
            int v = num_masks_p[0];
            if (v <= 0 || v > 1000000) {
                float f = __int_as_float(v);
                v = (int)f;
            }
            double nm = (double)max(v, 1);
            double ce = g_acc[0] / g_acc[1];
            double pair = g_acc[2] / fmax(g_acc[3], 1.0) / nm;
            double proj = g_acc[4] / nm;
            out[0] = (float)(ce + pair + proj);
        }
    }
}

// ---------------------------------------------------------------------------
extern "C" void kernel_launch(void* const* d_in, const int* in_sizes, int n_in,
                              void* d_out, int out_size) {
    const float* pred_logits = (const float*)d_in[0];   // (2,100,81)
    const float* src_masks   = (const float*)d_in[1];   // (64,256,256)
    const float* empty_w     = (const float*)d_in[2];   // (81,)
    const float* sims        = (const float*)d_in[3];   // (64,8,256,256)
    const int*   tgt_cls     = (const int*)d_in[4];     // (2,100)
    const int*   box         = (const int*)d_in[5];     // (64,256,256)
    const int*   num_masks   = (const int*)d_in[6];     // scalar
    float* out = (float*)d_out;

    setup_kernel<<<65, 256>>>(pred_logits, tgt_cls, empty_w);

    pair_kernel<<<dim3(WW / 128, HH / 8, NMASK), dim3(32, 8)>>>(src_masks, sims, box);

    projfinish_kernel<<<NMASK, 256>>>(num_masks, out);
}

// round 15
// speedup vs baseline: 1.5282x; 1.1048x over previous
#include <cuda_runtime.h>
#include <cuda_bf16.h>

#define HH 256
#define WW 256
#define NMASK 64
#define CDIM 81
#define BQ 200
#define HW (HH*WW)
#define CEB 25          // CE blocks (8 rows each)

// Accumulators (device globals; no mallocs allowed).
__device__ double g_acc[5];  // 2: pair sum, 3: tgt cnt, 4: proj sum (0,1 unused now)
__device__ float  g_cepart[CEB * 2];   // per-CE-block (wnll, wsum) — plain stores
__device__ unsigned g_rowmax[NMASK * HH];
__device__ unsigned g_colmax[NMASK * WW];
__device__ int g_rowbox[NMASK * HH];
__device__ int g_colbox[NMASK * WW];
__device__ int g_done;

__device__ __forceinline__ unsigned fenc(float f) {
    unsigned u = __float_as_uint(f);
    return (u & 0x80000000u) ? ~u : (u | 0x80000000u);
}
__device__ __forceinline__ float fdec(unsigned u) {
    return (u & 0x80000000u) ? __uint_as_float(u & 0x7fffffffu) : __uint_as_float(~u);
}
// Fast softplus: 2 MUFU + few FMA. Abs err ~1e-7, fine vs 1e-3 tolerance.
__device__ __forceinline__ float softplusf(float z) {
    return fmaxf(z, 0.f) + __logf(1.f + __expf(-fabsf(z)));
}

// ---------------------------------------------------------------------------
// Fused init + cross-entropy. Grid (64 + CEB) x 256:
//   blocks 0..63   : zero the row/col max/box arrays
//   blocks 64..88  : CE, one row per warp (no serial row loop)
__global__ void setup_kernel(const float* __restrict__ logits,
                             const int* __restrict__ cls,
                             const float* __restrict__ ew) {
    if (blockIdx.x < 64) {
        int i = blockIdx.x * 256 + threadIdx.x;   // covers 16384 = NMASK*HH exactly
        g_rowmax[i] = 0u; g_rowbox[i] = 0;
        g_colmax[i] = 0u; g_colbox[i] = 0;
        if (blockIdx.x == 0 && threadIdx.x == 0) {
            g_acc[2] = 0.0; g_acc[3] = 0.0; g_acc[4] = 0.0; g_done = 0;
        }
        return;
    }

    // CE: one row per warp, fully parallel.
    const int b = blockIdx.x - 64;               // 0..24
    const int wid = threadIdx.x >> 5, lane = threadIdx.x & 31;
    const int row = b * 8 + wid;                 // < 200
    const float* p = logits + row * CDIM;

    float v0 = p[lane];
    float v1 = p[lane + 32];
    float v2 = (lane < CDIM - 64) ? p[lane + 64] : -1e30f;
    float mx = fmaxf(v0, fmaxf(v1, v2));
    #pragma unroll
    for (int o = 16; o > 0; o >>= 1)
        mx = fmaxf(mx, __shfl_xor_sync(0xffffffff, mx, o));
    float se = __expf(v0 - mx) + __expf(v1 - mx) +
               ((lane < CDIM - 64) ? __expf(v2 - mx) : 0.f);
    #pragma unroll
    for (int o = 16; o > 0; o >>= 1)
        se += __shfl_xor_sync(0xffffffff, se, o);

    __shared__ float s1[8], s2[8];
    if (lane == 0) {
        int t = cls[row];
        float w = ew[t];
        s1[wid] = -w * (p[t] - mx - __logf(se));
        s2[wid] = w;
    }
    __syncthreads();
    if (threadIdx.x == 0) {
        float a = 0.f, bb = 0.f;
        #pragma unroll
        for (int i = 0; i < 8; i++) { a += s1[i]; bb += s2[i]; }
        g_cepart[b * 2 + 0] = a;
        g_cepart[b * 2 + 1] = bb;
    }
}

// ---------------------------------------------------------------------------
// Fused pairwise + projection-max pass. Tile: 128 wide x 8 high per block
// (256 threads, 4 px/thread, 128-bit loads). sims float4s are converted to
// threshold bits IMMEDIATELY after load (kills 32 regs of live payload ->
// higher occupancy). Inner loop is a bit-walk over surviving (box & thresh)
// pairs only. sim = sp(xc)+sp(xn)-sp(xc+xn); OOB neighbors contribute 0.
__global__ __launch_bounds__(256, 6)
void pair_kernel(const float* __restrict__ src,
                 const float* __restrict__ sims,
                 const int* __restrict__ box) {
    const int n = blockIdx.z;
    const int h0 = blockIdx.y * 8;
    const int w0 = blockIdx.x * 128;
    const int tx = threadIdx.x;       // 0..31
    const int ty = threadIdx.y;       // 0..7
    const int tid = ty * 32 + tx;

    __shared__ float sxf[12 * 132];   // src values, 2-px halo (flat)
    __shared__ float sspf[12 * 132];  // softplus(src)
    __shared__ int   sb[8][128];      // box tile
    __shared__ int   nboff[8];        // neighbor offsets in flat tile

    const int h = h0 + ty;
    const int wbase = w0 + tx * 4;

    if (tid < 8) {
        const int di[8] = {-2, -2, -2, 0, 0, 2, 2, 2};
        const int dj[8] = {-2, 0, 2, -2, 2, -2, 0, 2};
        nboff[tid] = di[tid] * 132 + dj[tid];
    }

    // Front-batched wide loads, converted to bits as they land.
    const float* simp = sims + (size_t)n * 8 * HW + h * WW + wbase;
    unsigned m = 0;
    #pragma unroll
    for (int p = 0; p < 8; p++) {
        float4 v = __ldcs((const float4*)(simp + (size_t)p * HW));
        m |= (v.x >= 0.3f ? 1u : 0u) << (0 * 8 + p);
        m |= (v.y >= 0.3f ? 1u : 0u) << (1 * 8 + p);
        m |= (v.z >= 0.3f ? 1u : 0u) << (2 * 8 + p);
        m |= (v.w >= 0.3f ? 1u : 0u) << (3 * 8 + p);
    }
    int4 b4 = __ldcs((const int4*)(box + (size_t)n * HW + h * WW + wbase));

    // Fill shared src tile (+ halo) and softplus.
    const float* srcn = src + (size_t)n * HW;
    for (int idx = tid; idx < 12 * 132; idx += 256) {
        int r = idx / 132, c = idx - r * 132;
        int gh = h0 - 2 + r, gw = w0 - 2 + c;
        float x = 0.f;
        if ((unsigned)gh < HH && (unsigned)gw < WW) x = srcn[gh * WW + gw];
        sxf[idx] = x;
        sspf[idx] = softplusf(x);
    }
    sb[ty][tx * 4 + 0] = b4.x;
    sb[ty][tx * 4 + 1] = b4.y;
    sb[ty][tx * 4 + 2] = b4.z;
    sb[ty][tx * 4 + 3] = b4.w;

    // Box gate (whole bytes) and tgt count (before OOB masking — reference
    // counts tgt over all taps including zero-padded ones).
    unsigned bm = (b4.x ? 0x000000FFu : 0u) | (b4.y ? 0x0000FF00u : 0u) |
                  (b4.z ? 0x00FF0000u : 0u) | (b4.w ? 0xFF000000u : 0u);
    m &= bm;
    float cnt = (float)__popc(m);
    int rbox = (b4.x | b4.y | b4.z | b4.w);

    // OOB allow-mask: only border threads lose bits.
    {
        unsigned rowbad = (h < 2 ? 0x07u : 0u) | (h > 253 ? 0xE0u : 0u);
        unsigned am = 0;
        #pragma unroll
        for (int i = 0; i < 4; i++) {
            int w = wbase + i;
            unsigned bad = rowbad | (w < 2 ? 0x29u : 0u) | (w > 253 ? 0x94u : 0u);
            am |= (0xFFu & ~bad) << (8 * i);
        }
        m &= am;
    }
    __syncthreads();

    // Bit-walk over surviving pairs.
    const int cbase = (ty + 2) * 132 + tx * 4 + 2;
    float sum = 0.f;
    float rmax = -1e30f;
    #pragma unroll
    for (int i = 0; i < 4; i++) rmax = fmaxf(rmax, sxf[cbase + i]);

    while (m) {
        int b = __ffs(m) - 1;
        m &= m - 1;
        int i = b >> 3, p = b & 7;
        int ci = cbase + i;
        int off = nboff[p];
        float xc = sxf[ci];
        float spc = sspf[ci];
        float xn = sxf[ci + off];
        float spn = sspf[ci + off];
        float z = xc + xn;
        sum += spc + spn - (fmaxf(z, 0.f) + __logf(1.f + __expf(-fabsf(z))));
    }

    // Per-row (warp) reduce: pairwise sums + row max/box.
    #pragma unroll
    for (int o = 16; o > 0; o >>= 1) {
        sum += __shfl_down_sync(0xffffffff, sum, o);
        cnt += __shfl_down_sync(0xffffffff, cnt, o);
        rmax = fmaxf(rmax, __shfl_xor_sync(0xffffffff, rmax, o));
        rbox |= __shfl_xor_sync(0xffffffff, rbox, o);
    }
    if (tx == 0) {
        atomicMax(&g_rowmax[n * HH + h], fenc(rmax));
        if (rbox) g_rowbox[n * HH + h] = 1;   // idempotent store
    }

    // Column partials from the shared tile (threads 0..127, one column each).
    if (tid < 128) {
        const int c = tid;
        float mx = -1e30f; int ob = 0;
        #pragma unroll
        for (int r = 0; r < 8; r++) {
            mx = fmaxf(mx, sxf[(r + 2) * 132 + c + 2]);
            ob |= sb[r][c];
        }
        atomicMax(&g_colmax[n * WW + w0 + c], fenc(mx));
        if (ob) g_colbox[n * WW + w0 + c] = 1;
    }

    // Block reduce pairwise sums -> one double atomic each.
    __shared__ float rs[8], rc[8];
    if (tx == 0) { rs[ty] = sum; rc[ty] = cnt; }
    __syncthreads();
    if (tid == 0) {
        float S = 0.f, C = 0.f;
        #pragma unroll
        for (int i2 = 0; i2 < 8; i2++) { S += rs[i2]; C += rc[i2]; }
        atomicAdd(&g_acc[2], (double)S);
        atomicAdd(&g_acc[3], (double)C);
    }
}

// ---------------------------------------------------------------------------
// Projection finish (64 blocks, one per n) with fused final: the LAST block
// to complete sums the CE partials and computes the output scalar.
__global__ void projfinish_kernel(const int* __restrict__ num_masks_p,
                                  float* __restrict__ out) {
    const int n = blockIdx.x;
    const int t = threadIdx.x;   // 0..255

    float mr = fdec(g_rowmax[n * HH + t]);
    float ix = 1.f / (1.f + __expf(-mr));
    float txv = (float)g_rowbox[n * HH + t];
    float a0 = ix * txv, a1 = ix * ix, a2 = txv * txv;

    float mc = fdec(g_colmax[n * WW + t]);
    float iy = 1.f / (1.f + __expf(-mc));
    float tyv = (float)g_colbox[n * WW + t];
    float b0 = iy * tyv, b1 = iy * iy, b2 = tyv * tyv;

    #pragma unroll
    for (int o = 16; o > 0; o >>= 1) {
        a0 += __shfl_down_sync(0xffffffff, a0, o);
        a1 += __shfl_down_sync(0xffffffff, a1, o);
        a2 += __shfl_down_sync(0xffffffff, a2, o);
        b0 += __shfl_down_sync(0xffffffff, b0, o);
        b1 += __shfl_down_sync(0xffffffff, b1, o);
        b2 += __shfl_down_sync(0xffffffff, b2, o);
    }
    __shared__ float r[6][8];
    int wid = t >> 5, lane = t & 31;
    if (lane == 0) {
        r[0][wid] = a0; r[1][wid] = a1; r[2][wid] = a2;
        r[3][wid] = b0; r[4][wid] = b1; r[5][wid] = b2;
    }
    __syncthreads();
    if (t == 0) {
        float s[6] = {0, 0, 0, 0, 0, 0};
        #pragma unroll
        for (int i = 0; i < 8; i++)
            #pragma unroll
            for (int k = 0; k < 6; k++) s[k] += r[k][i];
        double lx = 1.0 - 2.0 * (double)s[0] / ((double)s[1] + (double)s[2] + 1e-3);
        double ly = 1.0 - 2.0 * (double)s[3] / ((double)s[4] + (double)s[5] + 1e-3);
        atomicAdd(&g_acc[4], lx + ly);
        __threadfence();
        int prev = atomicAdd(&g_done, 1);
        if (prev == NMASK - 1) {
            // Sum CE partials (unrolled independent loads, L2-resident).
            float cn = 0.f, cw = 0.f;
            #pragma unroll
            for (int i = 0; i < CEB; i++) {
                cn += g_cepart[i * 2 + 0];
                cw += g_cepart[i * 2 + 1];
            }
            int v = num_masks_p[0];
            if (v <= 0 || v > 1000000) {
                float f = __int_as_float(v);
                v = (int)f;
            }
            double nm = (double)max(v, 1);
            double ce = (double)cn / (double)cw;
            double pair = g_acc[2] / fmax(g_acc[3], 1.0) / nm;
            double proj = g_acc[4] / nm;
            out[0] = (float)(ce + pair + proj);
        }
    }
}

// ---------------------------------------------------------------------------
extern "C" void kernel_launch(void* const* d_in, const int* in_sizes, int n_in,
                              void* d_out, int out_size) {
    const float* pred_logits = (const float*)d_in[0];   // (2,100,81)
    const float* src_masks   = (const float*)d_in[1];   // (64,256,256)
    const float* empty_w     = (const float*)d_in[2];   // (81,)
    const float* sims        = (const float*)d_in[3];   // (64,8,256,256)
    const int*   tgt_cls     = (const int*)d_in[4];     // (2,100)
    const int*   box         = (const int*)d_in[5];     // (64,256,256)
    const int*   num_masks   = (const int*)d_in[6];     // scalar
    float* out = (float*)d_out;

    setup_kernel<<<64 + CEB, 256>>>(pred_logits, tgt_cls, empty_w);

    pair_kernel<<<dim3(WW / 128, HH / 8, NMASK), dim3(32, 8)>>>(src_masks, sims, box);

    projfinish_kernel<<<NMASK, 256>>>(num_masks, out);
}